// round 2
// baseline (speedup 1.0000x reference)
#include <cuda_runtime.h>

// FixedPtSQP_Plus: batched SQP (6 iters) of box+simplex QP via primal-dual
// interior point (15 Newton steps). One CTA per batch element, 64 threads.
//
// Key structure exploited:
//   G = [I; -I]  =>  G' D G = diag(D1 + D2)   =>  H = Q0 + diag(d)  (64x64 SPD)
//   A = ones(1,64) =>  KKT solved by block elimination with 2 RHS.
// Cholesky kept in "raw column" form (column k never rescaled in smem;
// per-column inv-sqrt stored separately) => exactly one __syncthreads per
// factorization step, forward solve fused into the sweep.

#define NT 64

__device__ __forceinline__ float blockReduceSum(float v, float* slots) {
#pragma unroll
    for (int o = 16; o; o >>= 1) v += __shfl_xor_sync(0xffffffffu, v, o);
    __syncthreads();                       // protect slots from previous use
    if ((threadIdx.x & 31) == 0) slots[threadIdx.x >> 5] = v;
    __syncthreads();
    return slots[0] + slots[1];
}

__device__ __forceinline__ float blockReduceMin(float v, float* slots) {
#pragma unroll
    for (int o = 16; o; o >>= 1) v = fminf(v, __shfl_xor_sync(0xffffffffu, v, o));
    __syncthreads();
    if ((threadIdx.x & 31) == 0) slots[threadIdx.x >> 5] = v;
    __syncthreads();
    return fminf(slots[0], slots[1]);
}

__global__ __launch_bounds__(NT, 8)
void sqp_kernel(const float* __restrict__ c, const float* __restrict__ Q0,
                float* __restrict__ out)
{
    __shared__ float sH[64 * 65];          // H / Cholesky workspace (stride 65)
    __shared__ float sx[64];               // current x (broadcast for matvec)
    __shared__ float sz[64];               // current QP primal z (broadcast)
    __shared__ float su[64], sv[64];       // RHS residuals during factorization
    __shared__ float syu[64], syv[64];     // forward-solve outputs / backward residuals
    __shared__ float sdinv[64];            // 1/sqrt(diag_k) per column
    __shared__ float slots[2];             // reduction scratch

    const int b = blockIdx.x;
    const int t = threadIdx.x;
    const float* cb = c + b * 64;

    float x = 0.5f;
    float dlast = 0.0f;

    for (int sqp = 0; sqp < 6; ++sqp) {
        sx[t] = x;
        __syncthreads();

        // p = x @ Q0 - c   (Q0 symmetric; read column t -> coalesced, L1-hot)
        float p = 0.0f;
#pragma unroll 8
        for (int k = 0; k < 64; ++k) p += sx[k] * Q0[k * 64 + t];
        p -= cb[t];

        const float sumx = blockReduceSum(x, slots);
        const float beq = 1.0f - sumx;
        const float h1 = 1.0f - x, h2 = x;

        // QP state (thread t owns s/lam entries t and t+64)
        float z = 0.0f;
        float s1 = 1.0f, s2 = 1.0f, l1 = 1.0f, l2 = 1.0f, nu = 0.0f;
        sz[t] = 0.0f;
        __syncthreads();

        for (int it = 0; it < 15; ++it) {
            const float mu = 0.1f * blockReduceSum(s1 * l1 + s2 * l2, slots)
                             * (1.0f / 128.0f);

            // Q0 @ z (symmetry: use column t)
            float qz = 0.0f;
#pragma unroll 8
            for (int k = 0; k < 64; ++k) qz += sz[k] * Q0[k * 64 + t];

            const float r_dual = qz + p + (l1 - l2) + nu;
            const float rp1 = z + s1 - h1;
            const float rp2 = -z + s2 - h2;
            const float sumz = blockReduceSum(z, slots);
            const float r_peq = sumz - beq;
            const float rc1 = l1 * s1 - mu, rc2 = l2 * s2 - mu;
            const float w1 = (l1 * rp1 - rc1) / s1;
            const float w2 = (l2 * rp2 - rc2) / s2;
            const float rhs = -(r_dual + w1 - w2);
            const float Dsum = l1 / s1 + l2 / s2;

            // Build H = Q0 + diag(Dsum): thread t owns column t
#pragma unroll 8
            for (int i = 0; i < 64; ++i) {
                float q = Q0[i * 64 + t];
                sH[i * 65 + t] = (i == t) ? q + Dsum : q;
            }
            su[t] = rhs;
            sv[t] = 1.0f;
            __syncthreads();

            // Cholesky (raw columns) + fused forward solve, 1 sync per step
            for (int k = 0; k < 64; ++k) {
                const float diag = sH[k * 65 + k];
                const float suk = su[k], svk = sv[k];
                const float inv = __frsqrt_rn(diag);
                const float raw = sH[t * 65 + k];
                const float yu = suk * inv, yv = svk * inv;
                if (t == k) { syu[k] = yu; syv[k] = yv; sdinv[k] = inv; }
                if (t > k) {
                    const float lik = raw * inv;            // L[t][k]
                    su[t] -= lik * yu;
                    sv[t] -= lik * yv;
                    const float f = lik * inv;              // raw * inv^2
                    for (int j = k + 1; j <= t; ++j)
                        sH[t * 65 + j] -= f * sH[j * 65 + k];
                }
                __syncthreads();
            }

            // Backward solve L' x = y (two RHS), 1 sync per step
            const float mydinv = sdinv[t];
            float myU = 0.0f, myV = 0.0f;
            for (int k = 63; k >= 0; --k) {
                const float dk = sdinv[k];
                const float xu = syu[k] * dk;
                const float xv = syv[k] * dk;
                if (t == k) { myU = xu; myV = xv; }
                if (t < k) {
                    const float lkt = sH[k * 65 + t] * mydinv;  // L[k][t]
                    syu[t] -= lkt * xu;
                    syv[t] -= lkt * xv;
                }
                __syncthreads();
            }

            const float sum_u = blockReduceSum(myU, slots);
            const float sum_v = blockReduceSum(myV, slots);
            const float dnu = (sum_u + r_peq) / sum_v;
            const float dz = myU - dnu * myV;

            const float dl1 = (l1 * (rp1 + dz) - rc1) / s1;
            const float dl2 = (l2 * (rp2 - dz) - rc2) / s2;
            const float ds1 = -rp1 - dz;
            const float ds2 = -rp2 + dz;

            float am = 1.0f;
            if (dl1 < 0.0f) am = fminf(am, -l1 / dl1);
            if (dl2 < 0.0f) am = fminf(am, -l2 / dl2);
            if (ds1 < 0.0f) am = fminf(am, -s1 / ds1);
            if (ds2 < 0.0f) am = fminf(am, -s2 / ds2);
            const float a = 0.99f * fminf(1.0f, blockReduceMin(am, slots));

            z += a * dz;
            s1 += a * ds1; s2 += a * ds2;
            l1 += a * dl1; l2 += a * dl2;
            nu += a * dnu;
            sz[t] = z;
            __syncthreads();
        }

        x += z;          // ALPHA = 1
        dlast = z;       // d from this SQP iteration
        __syncthreads();
    }

    out[b * 64 + t] = x + dlast;
}

extern "C" void kernel_launch(void* const* d_in, const int* in_sizes, int n_in,
                              void* d_out, int out_size)
{
    const float* c  = (const float*)d_in[0];
    const float* Q0 = (const float*)d_in[1];
    int s0 = in_sizes[0];
    int s1 = (n_in > 1) ? in_sizes[1] : 0;
    // metadata order is (c, Q0); guard against the reverse by size signature
    if (s0 == 64 * 64 && s1 > 64 * 64) {
        const float* tmp = c; c = Q0; Q0 = tmp;
        int st = s0; s0 = s1; s1 = st;
    }
    const int B = s0 / 64;
    sqp_kernel<<<B, NT>>>(c, Q0, (float*)d_out);
}

// round 3
// speedup vs baseline: 2.0595x; 2.0595x over previous
#include <cuda_runtime.h>

// FixedPtSQP_Plus: batched SQP (6 iters x 15 Newton IPM steps), 1 CTA / batch elem.
// H = Q0 + diag(l1/s1 + l2/s2) (G=[I;-I]); A=1^T solved by block elimination (2 RHS).
// Rank-8 blocked Cholesky: 8x8 diagonal blocks factorized redundantly in registers
// (no intra-panel syncs), rank-8 trailing updates with float4 broadcast panel reads.
// Blocked backward solve (8 syncs). Shared traffic per FLOP cut ~6x vs rank-1.

#define NT 64

__device__ __forceinline__ void blockReduce2(float a, float b, float* slots,
                                             float& ra, float& rb) {
#pragma unroll
    for (int o = 16; o; o >>= 1) {
        a += __shfl_xor_sync(0xffffffffu, a, o);
        b += __shfl_xor_sync(0xffffffffu, b, o);
    }
    __syncthreads();
    const int w = threadIdx.x >> 5;
    if ((threadIdx.x & 31) == 0) { slots[w] = a; slots[2 + w] = b; }
    __syncthreads();
    ra = slots[0] + slots[1];
    rb = slots[2] + slots[3];
}

__device__ __forceinline__ float blockReduceMin(float v, float* slots) {
#pragma unroll
    for (int o = 16; o; o >>= 1) v = fminf(v, __shfl_xor_sync(0xffffffffu, v, o));
    __syncthreads();
    if ((threadIdx.x & 31) == 0) slots[threadIdx.x >> 5] = v;
    __syncthreads();
    return fminf(slots[0], slots[1]);
}

__global__ __launch_bounds__(NT, 7)
void sqp_kernel(const float* __restrict__ c, const float* __restrict__ Q0,
                float* __restrict__ out)
{
    __shared__ float sH[64 * 65];                    // H / L workspace, stride 65
    __shared__ __align__(16) float sP[64 * 8];       // panel L rows, stride 8 (f4)
    __shared__ float su[64], sv[64];                 // forward-solve residuals
    __shared__ float syu[64], syv[64];               // y = L^-1 rhs (then backward)
    __shared__ float sdinv[64];                      // 1/L[k][k]
    __shared__ float sx[64], sz[64];
    __shared__ float slots[4];

    const int b = blockIdx.x;
    const int t = threadIdx.x;
    const float cb = c[b * 64 + t];

    float x = 0.5f;
    float dlast = 0.0f;

    for (int sqp = 0; sqp < 6; ++sqp) {
        sx[t] = x;
        __syncthreads();

        // p = x @ Q0 - c (Q0 symmetric: column t, coalesced, L1-hot)
        float p = 0.0f;
#pragma unroll 8
        for (int k = 0; k < 64; ++k) p += sx[k] * Q0[k * 64 + t];
        p -= cb;

        float sumx, dum;
        blockReduce2(x, 0.0f, slots, sumx, dum);
        const float beq = 1.0f - sumx;
        const float h1 = 1.0f - x, h2 = x;

        float z = 0.0f;
        float s1 = 1.0f, s2 = 1.0f, l1 = 1.0f, l2 = 1.0f, nu = 0.0f;
        sz[t] = 0.0f;
        __syncthreads();

        for (int it = 0; it < 15; ++it) {
            float mu_s, sumz;
            blockReduce2(s1 * l1 + s2 * l2, z, slots, mu_s, sumz);
            const float mu = 0.1f * mu_s * (1.0f / 128.0f);

            float qz = 0.0f;
#pragma unroll 8
            for (int k = 0; k < 64; ++k) qz += sz[k] * Q0[k * 64 + t];

            const float r_dual = qz + p + (l1 - l2) + nu;
            const float rp1 = z + s1 - h1;
            const float rp2 = -z + s2 - h2;
            const float r_peq = sumz - beq;
            const float rc1 = l1 * s1 - mu, rc2 = l2 * s2 - mu;
            const float is1 = 1.0f / s1, is2 = 1.0f / s2;
            const float w1 = (l1 * rp1 - rc1) * is1;
            const float w2 = (l2 * rp2 - rc2) * is2;
            const float rhs = -(r_dual + w1 - w2);
            const float Dsum = l1 * is1 + l2 * is2;

            // Build H: thread t writes column t (conflict-free, coalesced LDG)
#pragma unroll 8
            for (int i = 0; i < 64; ++i) {
                float q = Q0[i * 64 + t];
                sH[i * 65 + t] = (i == t) ? q + Dsum : q;
            }
            su[t] = rhs;
            sv[t] = 1.0f;
            __syncthreads();

            float Lrow[8];
            float myXu = 0.0f, myXv = 0.0f;

            // ---- Forward: 8 panels, 2 syncs each ----
            for (int p8 = 0; p8 < 8; ++p8) {
                const int k0 = p8 << 3;

                if (t >= k0) {
                    // Redundant 8x8 diag-block Cholesky + in-block forward solve
                    float D8[8][8], suP[8], svP[8];
#pragma unroll
                    for (int i = 0; i < 8; ++i) {
#pragma unroll
                        for (int j = 0; j <= i; ++j)
                            D8[i][j] = sH[(k0 + i) * 65 + k0 + j];
                        suP[i] = su[k0 + i];
                        svP[i] = sv[k0 + i];
                    }
                    float inv8[8], yu8[8], yv8[8];
#pragma unroll
                    for (int k = 0; k < 8; ++k) {
                        const float inv = __frsqrt_rn(D8[k][k]);
                        inv8[k] = inv;
                        yu8[k] = suP[k] * inv;
                        yv8[k] = svP[k] * inv;
#pragma unroll
                        for (int i = k + 1; i < 8; ++i) {
                            const float Lik = D8[i][k] * inv;
                            D8[i][k] = Lik;
                            suP[i] -= Lik * yu8[k];
                            svP[i] -= Lik * yv8[k];
#pragma unroll
                            for (int j = k + 1; j <= i; ++j)
                                D8[i][j] -= Lik * D8[j][k];
                        }
                    }

                    if (t >= k0 + 8) {
                        // Solve my L row vs panel, mirror into sH and sP
                        float bb[8];
#pragma unroll
                        for (int j = 0; j < 8; ++j) bb[j] = sH[t * 65 + k0 + j];
#pragma unroll
                        for (int k = 0; k < 8; ++k) {
                            float v = bb[k];
#pragma unroll
                            for (int j = 0; j < k; ++j) v -= Lrow[j] * D8[k][j];
                            Lrow[k] = v * inv8[k];
                        }
#pragma unroll
                        for (int k = 0; k < 8; ++k) {
                            sH[t * 65 + k0 + k] = Lrow[k];
                            sP[t * 8 + k] = Lrow[k];
                        }
                        float du = 0.0f, dv = 0.0f;
#pragma unroll
                        for (int k = 0; k < 8; ++k) {
                            du = fmaf(Lrow[k], yu8[k], du);
                            dv = fmaf(Lrow[k], yv8[k], dv);
                        }
                        su[t] -= du;
                        sv[t] -= dv;
                    } else {
                        // I'm a panel row: publish L row, dinv, solved y
                        const int r = t - k0;
#pragma unroll
                        for (int k = 0; k < 8; ++k)
                            if (k < r) sH[t * 65 + k0 + k] = D8[r][k];
                        sdinv[t] = inv8[r];
                        syu[t] = yu8[r];
                        syv[t] = yv8[r];
                    }
                }
                __syncthreads();

                // Rank-8 trailing update (8 FMA per RMW)
                if (t >= k0 + 8) {
                    const float4* sP4 = (const float4*)sP;
                    for (int j = k0 + 8; j <= t; ++j) {
                        const float4 a = sP4[2 * j];
                        const float4 e = sP4[2 * j + 1];
                        float acc;
                        acc = Lrow[0] * a.x;
                        acc = fmaf(Lrow[1], a.y, acc);
                        acc = fmaf(Lrow[2], a.z, acc);
                        acc = fmaf(Lrow[3], a.w, acc);
                        acc = fmaf(Lrow[4], e.x, acc);
                        acc = fmaf(Lrow[5], e.y, acc);
                        acc = fmaf(Lrow[6], e.z, acc);
                        acc = fmaf(Lrow[7], e.w, acc);
                        sH[t * 65 + j] -= acc;
                    }
                }
                __syncthreads();
            }

            // ---- Backward: L' X = Y, 8 blocks top-down, 1 sync each ----
            for (int p8 = 7; p8 >= 0; --p8) {
                const int k0 = p8 << 3;
                if (t < k0 + 8) {
                    float T8[8][8], dinvP[8], yuP[8], yvP[8];
#pragma unroll
                    for (int i = 0; i < 8; ++i) {
#pragma unroll
                        for (int j = 0; j < i; ++j)
                            T8[i][j] = sH[(k0 + i) * 65 + k0 + j];
                        dinvP[i] = sdinv[k0 + i];
                        yuP[i] = syu[k0 + i];
                        yvP[i] = syv[k0 + i];
                    }
                    float xu8[8], xv8[8];
#pragma unroll
                    for (int i = 7; i >= 0; --i) {
                        float vu = yuP[i], vv = yvP[i];
#pragma unroll
                        for (int j = i + 1; j < 8; ++j) {
                            vu -= T8[j][i] * xu8[j];
                            vv -= T8[j][i] * xv8[j];
                        }
                        xu8[i] = vu * dinvP[i];
                        xv8[i] = vv * dinvP[i];
                    }
                    if (t >= k0) {
                        myXu = xu8[t - k0];
                        myXv = xv8[t - k0];
                    } else {
                        float du = 0.0f, dv = 0.0f;
#pragma unroll
                        for (int i = 0; i < 8; ++i) {
                            const float l = sH[(k0 + i) * 65 + t];
                            du = fmaf(l, xu8[i], du);
                            dv = fmaf(l, xv8[i], dv);
                        }
                        syu[t] -= du;
                        syv[t] -= dv;
                    }
                }
                __syncthreads();
            }

            float sum_u, sum_v;
            blockReduce2(myXu, myXv, slots, sum_u, sum_v);
            const float dnu = (sum_u + r_peq) / sum_v;
            const float dz = myXu - dnu * myXv;

            const float dl1 = (l1 * (rp1 + dz) - rc1) * is1;
            const float dl2 = (l2 * (rp2 - dz) - rc2) * is2;
            const float ds1 = -rp1 - dz;
            const float ds2 = -rp2 + dz;

            float am = 1.0f;
            if (dl1 < 0.0f) am = fminf(am, -l1 / dl1);
            if (dl2 < 0.0f) am = fminf(am, -l2 / dl2);
            if (ds1 < 0.0f) am = fminf(am, -s1 / ds1);
            if (ds2 < 0.0f) am = fminf(am, -s2 / ds2);
            const float a = 0.99f * fminf(1.0f, blockReduceMin(am, slots));

            z += a * dz;
            s1 += a * ds1; s2 += a * ds2;
            l1 += a * dl1; l2 += a * dl2;
            nu += a * dnu;
            sz[t] = z;
            __syncthreads();
        }

        x += z;          // ALPHA = 1
        dlast = z;
        __syncthreads();
    }

    out[b * 64 + t] = x + dlast;
}

extern "C" void kernel_launch(void* const* d_in, const int* in_sizes, int n_in,
                              void* d_out, int out_size)
{
    const float* c  = (const float*)d_in[0];
    const float* Q0 = (const float*)d_in[1];
    int s0 = in_sizes[0];
    int s1 = (n_in > 1) ? in_sizes[1] : 0;
    if (s0 == 64 * 64 && s1 > 64 * 64) {   // guard against swapped metadata order
        const float* tmp = c; c = Q0; Q0 = tmp;
        int st = s0; s0 = s1; s1 = st;
    }
    const int B = s0 / 64;
    sqp_kernel<<<B, NT>>>(c, Q0, (float*)d_out);
}

// round 4
// speedup vs baseline: 2.2874x; 1.1106x over previous
#include <cuda_runtime.h>

// FixedPtSQP_Plus: batched SQP (6 x 15 Newton IPM), 1 CTA (64 thr) per batch elem.
// H = Q0 + diag(l1/s1+l2/s2); A=1^T -> block elimination with 2 RHS.
// Rank-8 blocked Cholesky (redundant 8x8 register factorization, float4 panel).
// NEW: Q0 lives in sH's upper triangle for the whole kernel (factorization only
// touches lower); lower is restored by symmetry each Newton step and the
// Q0-matvecs read the upper triangle -> zero global traffic inside Newton loop.

#define NT 64

__device__ __forceinline__ void blockReduce2(float a, float b, float* slots,
                                             float& ra, float& rb) {
#pragma unroll
    for (int o = 16; o; o >>= 1) {
        a += __shfl_xor_sync(0xffffffffu, a, o);
        b += __shfl_xor_sync(0xffffffffu, b, o);
    }
    __syncthreads();
    const int w = threadIdx.x >> 5;
    if ((threadIdx.x & 31) == 0) { slots[w] = a; slots[2 + w] = b; }
    __syncthreads();
    ra = slots[0] + slots[1];
    rb = slots[2] + slots[3];
}

__device__ __forceinline__ float blockReduceMin(float v, float* slots) {
#pragma unroll
    for (int o = 16; o; o >>= 1) v = fminf(v, __shfl_xor_sync(0xffffffffu, v, o));
    __syncthreads();
    if ((threadIdx.x & 31) == 0) slots[threadIdx.x >> 5] = v;
    __syncthreads();
    return fminf(slots[0], slots[1]);
}

__global__ __launch_bounds__(NT, 7)
void sqp_kernel(const float* __restrict__ c, const float* __restrict__ Q0,
                float* __restrict__ out)
{
    __shared__ float sH[64 * 65];                 // upper: Q0 (persistent); lower: L
    __shared__ __align__(16) float sP[64 * 8];    // panel L rows, stride 8 (float4)
    __shared__ float su[64], sv[64];
    __shared__ float syu[64], syv[64];
    __shared__ float sdinv[64];
    __shared__ float sx[64], sz[64];
    __shared__ float slots[4];

    const int b = blockIdx.x;
    const int t = threadIdx.x;
    const float cb = c[b * 64 + t];
    const float qdiag = Q0[t * 64 + t];

    // One-time full copy of Q0 into sH (coalesced LDG, conflict-free STS).
#pragma unroll 8
    for (int i = 0; i < 64; ++i) sH[i * 65 + t] = Q0[i * 64 + t];

    float x = 0.5f;
    float dlast = 0.0f;
    __syncthreads();

    for (int sqp = 0; sqp < 6; ++sqp) {
        sx[t] = x;
        __syncthreads();

        // p = Q0 x - c via symmetric sH read (upper triangle + qdiag)
        float p = qdiag * x;
#pragma unroll 4
        for (int k = 0; k < t; ++k) p = fmaf(sH[k * 65 + t], sx[k], p);
#pragma unroll 4
        for (int k = t + 1; k < 64; ++k) p = fmaf(sH[t * 65 + k], sx[k], p);
        p -= cb;

        float sumx, dum;
        blockReduce2(x, 0.0f, slots, sumx, dum);
        const float beq = 1.0f - sumx;
        const float h1 = 1.0f - x, h2 = x;

        float z = 0.0f;
        float s1 = 1.0f, s2 = 1.0f, l1 = 1.0f, l2 = 1.0f, nu = 0.0f;
        sz[t] = 0.0f;
        __syncthreads();

        for (int it = 0; it < 15; ++it) {
            float mu_s, sumz;
            blockReduce2(s1 * l1 + s2 * l2, z, slots, mu_s, sumz);
            const float mu = 0.1f * mu_s * (1.0f / 128.0f);

            // qz = Q0 z via symmetric sH read (reads strictly-upper only)
            float qz = qdiag * z;
#pragma unroll 4
            for (int k = 0; k < t; ++k) qz = fmaf(sH[k * 65 + t], sz[k], qz);
#pragma unroll 4
            for (int k = t + 1; k < 64; ++k) qz = fmaf(sH[t * 65 + k], sz[k], qz);

            const float r_dual = qz + p + (l1 - l2) + nu;
            const float rp1 = z + s1 - h1;
            const float rp2 = -z + s2 - h2;
            const float r_peq = sumz - beq;
            const float rc1 = l1 * s1 - mu, rc2 = l2 * s2 - mu;
            const float is1 = 1.0f / s1, is2 = 1.0f / s2;
            const float w1 = (l1 * rp1 - rc1) * is1;
            const float w2 = (l2 * rp2 - rc2) * is2;
            const float rhs = -(r_dual + w1 - w2);
            const float Dsum = l1 * is1 + l2 * is2;

            // Restore lower triangle from upper (writes strictly-lower + diag;
            // concurrent symmetric matvec reads are strictly-upper -> disjoint)
#pragma unroll 4
            for (int j = 0; j < t; ++j) sH[t * 65 + j] = sH[j * 65 + t];
            sH[t * 65 + t] = qdiag + Dsum;
            su[t] = rhs;
            sv[t] = 1.0f;
            __syncthreads();

            float Lrow[8];
            float myXu = 0.0f, myXv = 0.0f;

            // ---- Forward: 8 panels, 2 syncs each ----
            for (int p8 = 0; p8 < 8; ++p8) {
                const int k0 = p8 << 3;

                if (t >= k0) {
                    float D8[8][8], suP[8], svP[8];
#pragma unroll
                    for (int i = 0; i < 8; ++i) {
#pragma unroll
                        for (int j = 0; j <= i; ++j)
                            D8[i][j] = sH[(k0 + i) * 65 + k0 + j];
                        suP[i] = su[k0 + i];
                        svP[i] = sv[k0 + i];
                    }
                    float inv8[8], yu8[8], yv8[8];
#pragma unroll
                    for (int k = 0; k < 8; ++k) {
                        const float inv = __frsqrt_rn(D8[k][k]);
                        inv8[k] = inv;
                        yu8[k] = suP[k] * inv;
                        yv8[k] = svP[k] * inv;
#pragma unroll
                        for (int i = k + 1; i < 8; ++i) {
                            const float Lik = D8[i][k] * inv;
                            D8[i][k] = Lik;
                            suP[i] -= Lik * yu8[k];
                            svP[i] -= Lik * yv8[k];
#pragma unroll
                            for (int j = k + 1; j <= i; ++j)
                                D8[i][j] -= Lik * D8[j][k];
                        }
                    }

                    if (t >= k0 + 8) {
                        float bb[8];
#pragma unroll
                        for (int j = 0; j < 8; ++j) bb[j] = sH[t * 65 + k0 + j];
#pragma unroll
                        for (int k = 0; k < 8; ++k) {
                            float v = bb[k];
#pragma unroll
                            for (int j = 0; j < k; ++j) v -= Lrow[j] * D8[k][j];
                            Lrow[k] = v * inv8[k];
                        }
#pragma unroll
                        for (int k = 0; k < 8; ++k) {
                            sH[t * 65 + k0 + k] = Lrow[k];
                            sP[t * 8 + k] = Lrow[k];
                        }
                        float du = 0.0f, dv = 0.0f;
#pragma unroll
                        for (int k = 0; k < 8; ++k) {
                            du = fmaf(Lrow[k], yu8[k], du);
                            dv = fmaf(Lrow[k], yv8[k], dv);
                        }
                        su[t] -= du;
                        sv[t] -= dv;
                    } else {
                        const int r = t - k0;
#pragma unroll
                        for (int k = 0; k < 8; ++k)
                            if (k < r) sH[t * 65 + k0 + k] = D8[r][k];
                        sdinv[t] = inv8[r];
                        syu[t] = yu8[r];
                        syv[t] = yv8[r];
                    }
                }
                __syncthreads();

                // Rank-8 trailing update, manually unrolled x2 with batched loads
                if (t >= k0 + 8) {
                    const float4* sP4 = (const float4*)sP;
                    float* row = &sH[t * 65];
                    int j = k0 + 8;
                    const int end = t;
                    for (; j + 1 <= end; j += 2) {
                        const float4 a0 = sP4[2 * j];
                        const float4 e0 = sP4[2 * j + 1];
                        const float4 a1 = sP4[2 * j + 2];
                        const float4 e1 = sP4[2 * j + 3];
                        const float h0 = row[j];
                        const float h1v = row[j + 1];
                        float acc0 = Lrow[0] * a0.x;
                        float acc1 = Lrow[0] * a1.x;
                        acc0 = fmaf(Lrow[1], a0.y, acc0);
                        acc1 = fmaf(Lrow[1], a1.y, acc1);
                        acc0 = fmaf(Lrow[2], a0.z, acc0);
                        acc1 = fmaf(Lrow[2], a1.z, acc1);
                        acc0 = fmaf(Lrow[3], a0.w, acc0);
                        acc1 = fmaf(Lrow[3], a1.w, acc1);
                        acc0 = fmaf(Lrow[4], e0.x, acc0);
                        acc1 = fmaf(Lrow[4], e1.x, acc1);
                        acc0 = fmaf(Lrow[5], e0.y, acc0);
                        acc1 = fmaf(Lrow[5], e1.y, acc1);
                        acc0 = fmaf(Lrow[6], e0.z, acc0);
                        acc1 = fmaf(Lrow[6], e1.z, acc1);
                        acc0 = fmaf(Lrow[7], e0.w, acc0);
                        acc1 = fmaf(Lrow[7], e1.w, acc1);
                        row[j] = h0 - acc0;
                        row[j + 1] = h1v - acc1;
                    }
                    if (j <= end) {
                        const float4 a = sP4[2 * j];
                        const float4 e = sP4[2 * j + 1];
                        float acc = Lrow[0] * a.x;
                        acc = fmaf(Lrow[1], a.y, acc);
                        acc = fmaf(Lrow[2], a.z, acc);
                        acc = fmaf(Lrow[3], a.w, acc);
                        acc = fmaf(Lrow[4], e.x, acc);
                        acc = fmaf(Lrow[5], e.y, acc);
                        acc = fmaf(Lrow[6], e.z, acc);
                        acc = fmaf(Lrow[7], e.w, acc);
                        row[j] -= acc;
                    }
                }
                __syncthreads();
            }

            // ---- Backward: L' X = Y, 8 blocks, 1 sync each ----
            for (int p8 = 7; p8 >= 0; --p8) {
                const int k0 = p8 << 3;
                if (t < k0 + 8) {
                    float T8[8][8], dinvP[8], yuP[8], yvP[8];
#pragma unroll
                    for (int i = 0; i < 8; ++i) {
#pragma unroll
                        for (int j = 0; j < i; ++j)
                            T8[i][j] = sH[(k0 + i) * 65 + k0 + j];
                        dinvP[i] = sdinv[k0 + i];
                        yuP[i] = syu[k0 + i];
                        yvP[i] = syv[k0 + i];
                    }
                    float xu8[8], xv8[8];
#pragma unroll
                    for (int i = 7; i >= 0; --i) {
                        float vu = yuP[i], vv = yvP[i];
#pragma unroll
                        for (int j = i + 1; j < 8; ++j) {
                            vu -= T8[j][i] * xu8[j];
                            vv -= T8[j][i] * xv8[j];
                        }
                        xu8[i] = vu * dinvP[i];
                        xv8[i] = vv * dinvP[i];
                    }
                    if (t >= k0) {
                        myXu = xu8[t - k0];
                        myXv = xv8[t - k0];
                    } else {
                        float du = 0.0f, dv = 0.0f;
#pragma unroll
                        for (int i = 0; i < 8; ++i) {
                            const float l = sH[(k0 + i) * 65 + t];
                            du = fmaf(l, xu8[i], du);
                            dv = fmaf(l, xv8[i], dv);
                        }
                        syu[t] -= du;
                        syv[t] -= dv;
                    }
                }
                __syncthreads();
            }

            float sum_u, sum_v;
            blockReduce2(myXu, myXv, slots, sum_u, sum_v);
            const float dnu = (sum_u + r_peq) / sum_v;
            const float dz = myXu - dnu * myXv;

            const float dl1 = (l1 * (rp1 + dz) - rc1) * is1;
            const float dl2 = (l2 * (rp2 - dz) - rc2) * is2;
            const float ds1 = -rp1 - dz;
            const float ds2 = -rp2 + dz;

            float am = 1.0f;
            if (dl1 < 0.0f) am = fminf(am, -l1 / dl1);
            if (dl2 < 0.0f) am = fminf(am, -l2 / dl2);
            if (ds1 < 0.0f) am = fminf(am, -s1 / ds1);
            if (ds2 < 0.0f) am = fminf(am, -s2 / ds2);
            const float a = 0.99f * fminf(1.0f, blockReduceMin(am, slots));

            z += a * dz;
            s1 += a * ds1; s2 += a * ds2;
            l1 += a * dl1; l2 += a * dl2;
            nu += a * dnu;
            sz[t] = z;
            __syncthreads();
        }

        x += z;          // ALPHA = 1
        dlast = z;
        __syncthreads();
    }

    out[b * 64 + t] = x + dlast;
}

extern "C" void kernel_launch(void* const* d_in, const int* in_sizes, int n_in,
                              void* d_out, int out_size)
{
    const float* c  = (const float*)d_in[0];
    const float* Q0 = (const float*)d_in[1];
    int s0 = in_sizes[0];
    int s1 = (n_in > 1) ? in_sizes[1] : 0;
    if (s0 == 64 * 64 && s1 > 64 * 64) {   // guard against swapped metadata order
        const float* tmp = c; c = Q0; Q0 = tmp;
        int st = s0; s0 = s1; s1 = st;
    }
    const int B = s0 / 64;
    sqp_kernel<<<B, NT>>>(c, Q0, (float*)d_out);
}

// round 5
// speedup vs baseline: 2.5737x; 1.1252x over previous
#include <cuda_runtime.h>

// FixedPtSQP_Plus: batched SQP (6 x 15 Newton IPM), 1 CTA (128 thr) / batch elem.
// Thread pair (tr, tr+64) co-owns matrix row tr. H = Q0 + diag(.) ; A=1^T ->
// block elimination, 2 RHS. Rank-8 blocked Cholesky:
//  - 8x8 diag block factorized warp-cooperatively via shuffles (8 regs, no spills)
//  - row-solve / backward read the block from shared (broadcast LDS)
//  - trailing update split between the thread pair (halved critical path)
// Q0 persists in sH's upper triangle; lower restored by symmetry each step.

#define NT 128

__device__ __forceinline__ void blockReduce2(float a, float b, float* slots,
                                             float& ra, float& rb) {
#pragma unroll
    for (int o = 16; o; o >>= 1) {
        a += __shfl_xor_sync(0xffffffffu, a, o);
        b += __shfl_xor_sync(0xffffffffu, b, o);
    }
    __syncthreads();
    const int w = threadIdx.x >> 5;
    if ((threadIdx.x & 31) == 0) { slots[w] = a; slots[4 + w] = b; }
    __syncthreads();
    ra = (slots[0] + slots[1]) + (slots[2] + slots[3]);
    rb = (slots[4] + slots[5]) + (slots[6] + slots[7]);
}

__device__ __forceinline__ float blockReduceMin(float v, float* slots) {
#pragma unroll
    for (int o = 16; o; o >>= 1) v = fminf(v, __shfl_xor_sync(0xffffffffu, v, o));
    __syncthreads();
    if ((threadIdx.x & 31) == 0) slots[threadIdx.x >> 5] = v;
    __syncthreads();
    return fminf(fminf(slots[0], slots[1]), fminf(slots[2], slots[3]));
}

__global__ __launch_bounds__(NT, 7)
void sqp_kernel(const float* __restrict__ c, const float* __restrict__ Q0,
                float* __restrict__ out)
{
    __shared__ float sH[64 * 65];                 // upper: Q0 persistent; lower: L
    __shared__ __align__(16) float sP[64 * 8];    // panel L rows, stride 8 (float4)
    __shared__ float su[64], sv[64];
    __shared__ float syu[64], syv[64];
    __shared__ float sdinv[64];
    __shared__ float sx[64], sz[64];
    __shared__ float spart[128];
    __shared__ float slots[8];

    const int b = blockIdx.x;
    const int t = threadIdx.x;
    const int tr = t & 63;                        // row owned by the pair
    const int hi = t >> 6;                        // 0 = primary, 1 = helper
    const int wid = t >> 5;
    const int lane = t & 31;

    const float cb = c[b * 64 + tr];
    const float qdiag = Q0[tr * 64 + tr];

    // One-time copy Q0 -> sH (split by row-halves, coalesced)
    {
        const int i0 = hi << 5;
#pragma unroll 8
        for (int i = 0; i < 32; ++i)
            sH[(i0 + i) * 65 + tr] = Q0[(i0 + i) * 64 + tr];
    }

    float x = 0.5f;          // meaningful on hi==0 only
    float dlast = 0.0f;
    __syncthreads();

    const int kbeg = hi << 5, kend = kbeg + 32;

    for (int sqp = 0; sqp < 6; ++sqp) {
        if (!hi) sx[tr] = x;
        __syncthreads();

        // p = Q0 x - c : symmetric read of upper triangle, split by k-halves
        float pp = 0.0f;
        {
            const int m1 = min(kend, tr);
            for (int k = kbeg; k < m1; ++k) pp = fmaf(sH[k * 65 + tr], sx[k], pp);
            if (tr >= kbeg && tr < kend) pp = fmaf(qdiag, sx[tr], pp);
            for (int k = max(kbeg, tr + 1); k < kend; ++k)
                pp = fmaf(sH[tr * 65 + k], sx[k], pp);
        }
        spart[t] = pp;

        float sumx, dum;
        blockReduce2(hi ? 0.0f : x, 0.0f, slots, sumx, dum);
        const float p = spart[tr] + spart[64 + tr] - cb;    // valid on lo
        const float beq = 1.0f - sumx;
        const float h1 = 1.0f - x, h2 = x;

        float z = 0.0f, s1 = 1.0f, s2 = 1.0f, l1 = 1.0f, l2 = 1.0f, nu = 0.0f;
        if (!hi) sz[tr] = 0.0f;
        __syncthreads();

        for (int it = 0; it < 15; ++it) {
            // qz = Q0 z : symmetric, split halves
            float qzp = 0.0f;
            {
                const int m1 = min(kend, tr);
                for (int k = kbeg; k < m1; ++k) qzp = fmaf(sH[k * 65 + tr], sz[k], qzp);
                if (tr >= kbeg && tr < kend) qzp = fmaf(qdiag, sz[tr], qzp);
                for (int k = max(kbeg, tr + 1); k < kend; ++k)
                    qzp = fmaf(sH[tr * 65 + k], sz[k], qzp);
            }
            spart[t] = qzp;

            float mu_s, sumz;
            blockReduce2(hi ? 0.0f : (s1 * l1 + s2 * l2), hi ? 0.0f : z,
                         slots, mu_s, sumz);
            const float mu = 0.1f * mu_s * (1.0f / 128.0f);
            const float qz = spart[tr] + spart[64 + tr];

            float rp1 = 0.f, rp2 = 0.f, rc1 = 0.f, rc2 = 0.f;
            float is1 = 0.f, is2 = 0.f, r_peq = 0.f;
            if (!hi) {
                const float r_dual = qz + p + (l1 - l2) + nu;
                rp1 = z + s1 - h1;
                rp2 = -z + s2 - h2;
                r_peq = sumz - beq;
                rc1 = l1 * s1 - mu; rc2 = l2 * s2 - mu;
                is1 = 1.0f / s1;    is2 = 1.0f / s2;
                const float w1 = (l1 * rp1 - rc1) * is1;
                const float w2 = (l2 * rp2 - rc2) * is2;
                su[tr] = -(r_dual + w1 - w2);
                sv[tr] = 1.0f;
                sH[tr * 65 + tr] = qdiag + (l1 * is1 + l2 * is2);
            }
            // Restore lower triangle from upper (pair-split; reads upper only)
            {
                const int jb = hi ? (tr >> 1) : 0;
                const int je = hi ? tr : (tr >> 1);
                for (int j = jb; j < je; ++j) sH[tr * 65 + j] = sH[j * 65 + tr];
            }
            __syncthreads();

            float myXu = 0.0f, myXv = 0.0f;

            // ---- Forward sweep over 8 panels ----
            for (int p8 = 0; p8 < 8; ++p8) {
                const int k0 = p8 << 3;

                // Warp-cooperative 8x8 factorization (owning warp only)
                if (wid == (k0 >> 5)) {
                    const int base = k0 & 31;
                    const int r = lane - base;
                    const bool valid = ((unsigned)r < 8u);
                    float row[8];
                    float myu = 0.f, myv = 0.f;
                    if (valid) {
#pragma unroll
                        for (int j = 0; j < 8; ++j)
                            row[j] = sH[(k0 + r) * 65 + k0 + j];
                        myu = su[k0 + r];
                        myv = sv[k0 + r];
                    }
                    float inv_r = 0.f, yu_r = 0.f, yv_r = 0.f;
#pragma unroll
                    for (int k = 0; k < 8; ++k) {
                        const float dkk = __shfl_sync(0xffffffffu, row[k], base + k);
                        const float inv = __frsqrt_rn(dkk);
                        const float yuk = __shfl_sync(0xffffffffu, myu, base + k) * inv;
                        const float yvk = __shfl_sync(0xffffffffu, myv, base + k) * inv;
                        if (r == k) { inv_r = inv; yu_r = yuk; yv_r = yvk; }
                        const float Ljk = row[k] * inv;   // lane j holds L[j][k]
#pragma unroll
                        for (int j = k + 1; j < 8; ++j) {
                            const float Lj = __shfl_sync(0xffffffffu, Ljk, base + j);
                            if (r >= j) row[j] = fmaf(-Ljk, Lj, row[j]);
                        }
                        if (r > k) {
                            row[k] = Ljk;                 // keep scaled L
                            myu = fmaf(-Ljk, yuk, myu);
                            myv = fmaf(-Ljk, yvk, myv);
                        }
                    }
                    if (valid) {
#pragma unroll
                        for (int j = 0; j < 8; ++j)
                            if (j < r) sH[(k0 + r) * 65 + k0 + j] = row[j];
                        sdinv[k0 + r] = inv_r;
                        syu[k0 + r] = yu_r;
                        syv[k0 + r] = yv_r;
                    }
                }
                __syncthreads();

                if (k0 + 8 >= 64) break;   // last panel: nothing below

                // Row-solve vs panel (both halves; shared broadcast reads)
                float Lrow[8];
                if (tr >= k0 + 8) {
                    float bb[8];
#pragma unroll
                    for (int j = 0; j < 8; ++j) bb[j] = sH[tr * 65 + k0 + j];
#pragma unroll
                    for (int k = 0; k < 8; ++k) {
                        float v = bb[k];
#pragma unroll
                        for (int j = 0; j < k; ++j)
                            v = fmaf(-Lrow[j], sH[(k0 + k) * 65 + k0 + j], v);
                        Lrow[k] = v * sdinv[k0 + k];
                    }
                    if (!hi) {
                        float du = 0.f, dv = 0.f;
#pragma unroll
                        for (int k = 0; k < 8; ++k) {
                            sH[tr * 65 + k0 + k] = Lrow[k];
                            sP[tr * 8 + k] = Lrow[k];
                            du = fmaf(Lrow[k], syu[k0 + k], du);
                            dv = fmaf(Lrow[k], syv[k0 + k], dv);
                        }
                        su[tr] -= du;
                        sv[tr] -= dv;
                    }
                }
                __syncthreads();

                // Rank-8 trailing update, columns split between the pair
                if (tr >= k0 + 8) {
                    const float4* sP4 = (const float4*)sP;
                    float* rowp = &sH[tr * 65];
                    const int n = tr - (k0 + 8) + 1;
                    const int nlo = (n + 1) >> 1;
                    int j = hi ? (k0 + 8 + nlo) : (k0 + 8);
                    const int end = hi ? tr : (k0 + 7 + nlo);   // inclusive
                    for (; j + 1 <= end; j += 2) {
                        const float4 a0 = sP4[2 * j];
                        const float4 e0 = sP4[2 * j + 1];
                        const float4 a1 = sP4[2 * j + 2];
                        const float4 e1 = sP4[2 * j + 3];
                        const float h0 = rowp[j];
                        const float h1v = rowp[j + 1];
                        float acc0 = Lrow[0] * a0.x;
                        float acc1 = Lrow[0] * a1.x;
                        acc0 = fmaf(Lrow[1], a0.y, acc0); acc1 = fmaf(Lrow[1], a1.y, acc1);
                        acc0 = fmaf(Lrow[2], a0.z, acc0); acc1 = fmaf(Lrow[2], a1.z, acc1);
                        acc0 = fmaf(Lrow[3], a0.w, acc0); acc1 = fmaf(Lrow[3], a1.w, acc1);
                        acc0 = fmaf(Lrow[4], e0.x, acc0); acc1 = fmaf(Lrow[4], e1.x, acc1);
                        acc0 = fmaf(Lrow[5], e0.y, acc0); acc1 = fmaf(Lrow[5], e1.y, acc1);
                        acc0 = fmaf(Lrow[6], e0.z, acc0); acc1 = fmaf(Lrow[6], e1.z, acc1);
                        acc0 = fmaf(Lrow[7], e0.w, acc0); acc1 = fmaf(Lrow[7], e1.w, acc1);
                        rowp[j] = h0 - acc0;
                        rowp[j + 1] = h1v - acc1;
                    }
                    if (j <= end) {
                        const float4 a = sP4[2 * j];
                        const float4 e = sP4[2 * j + 1];
                        float acc = Lrow[0] * a.x;
                        acc = fmaf(Lrow[1], a.y, acc);
                        acc = fmaf(Lrow[2], a.z, acc);
                        acc = fmaf(Lrow[3], a.w, acc);
                        acc = fmaf(Lrow[4], e.x, acc);
                        acc = fmaf(Lrow[5], e.y, acc);
                        acc = fmaf(Lrow[6], e.z, acc);
                        acc = fmaf(Lrow[7], e.w, acc);
                        rowp[j] -= acc;
                    }
                }
                __syncthreads();
            }

            // ---- Backward: L' X = Y, 8 blocks top-down ----
            for (int p8 = 7; p8 >= 0; --p8) {
                const int k0 = p8 << 3;
                if (!hi && tr < k0 + 8) {
                    // redundant 8x8 transpose solve from shared (broadcast LDS)
                    float xu8[8], xv8[8];
#pragma unroll
                    for (int i = 7; i >= 0; --i) {
                        float vu = syu[k0 + i], vv = syv[k0 + i];
#pragma unroll
                        for (int j = i + 1; j < 8; ++j) {
                            const float l = sH[(k0 + j) * 65 + k0 + i];
                            vu = fmaf(-l, xu8[j], vu);
                            vv = fmaf(-l, xv8[j], vv);
                        }
                        const float dk = sdinv[k0 + i];
                        xu8[i] = vu * dk;
                        xv8[i] = vv * dk;
                    }
                    if (tr >= k0) {
                        myXu = xu8[tr - k0];
                        myXv = xv8[tr - k0];
                    } else {
                        float du = 0.f, dv = 0.f;
#pragma unroll
                        for (int i = 0; i < 8; ++i) {
                            const float l = sH[(k0 + i) * 65 + tr];
                            du = fmaf(l, xu8[i], du);
                            dv = fmaf(l, xv8[i], dv);
                        }
                        syu[tr] -= du;
                        syv[tr] -= dv;
                    }
                }
                __syncthreads();
            }

            float sum_u, sum_v;
            blockReduce2(myXu, myXv, slots, sum_u, sum_v);

            float am = 3.0e38f;
            float dz = 0.f, dl1 = 0.f, dl2 = 0.f, ds1 = 0.f, ds2 = 0.f, dnu = 0.f;
            if (!hi) {
                dnu = (sum_u + r_peq) / sum_v;
                dz = myXu - dnu * myXv;
                dl1 = (l1 * (rp1 + dz) - rc1) * is1;
                dl2 = (l2 * (rp2 - dz) - rc2) * is2;
                ds1 = -rp1 - dz;
                ds2 = -rp2 + dz;
                am = 1.0f;
                if (dl1 < 0.0f) am = fminf(am, -l1 / dl1);
                if (dl2 < 0.0f) am = fminf(am, -l2 / dl2);
                if (ds1 < 0.0f) am = fminf(am, -s1 / ds1);
                if (ds2 < 0.0f) am = fminf(am, -s2 / ds2);
            }
            const float a = 0.99f * fminf(1.0f, blockReduceMin(am, slots));

            if (!hi) {
                z += a * dz;
                s1 += a * ds1; s2 += a * ds2;
                l1 += a * dl1; l2 += a * dl2;
                nu += a * dnu;
                sz[tr] = z;
            }
            __syncthreads();
        }

        if (!hi) { x += z; dlast = z; }     // ALPHA = 1
        __syncthreads();
    }

    if (!hi) out[b * 64 + tr] = x + dlast;
}

extern "C" void kernel_launch(void* const* d_in, const int* in_sizes, int n_in,
                              void* d_out, int out_size)
{
    const float* c  = (const float*)d_in[0];
    const float* Q0 = (const float*)d_in[1];
    int s0 = in_sizes[0];
    int s1 = (n_in > 1) ? in_sizes[1] : 0;
    if (s0 == 64 * 64 && s1 > 64 * 64) {   // guard against swapped metadata order
        const float* tmp = c; c = Q0; Q0 = tmp;
        int st = s0; s0 = s1; s1 = st;
    }
    const int B = s0 / 64;
    sqp_kernel<<<B, NT>>>(c, Q0, (float*)d_out);
}